// round 8
// baseline (speedup 1.0000x reference)
#include <cuda_runtime.h>
#include <cuda_bf16.h>

// GraphAddPooling: out[g] = sum_{i: batch[i]==g} x[i]
// x: [200000, 256] fp32, batch: sorted (int32/int64, detected), out: [512,256] fp32.
//
// One block per (segment, column half): 1024 blocks x 256 threads, 8 CTAs/SM,
// single wave. Warp 0 finds BOTH bounds with a seeded split-warp k-ary search
// (lanes 0-15: g, lanes 16-31: g+1; window E +/- 1500, validity probes, full
// fallback). Warps then stream rows lo+w+8k: steady state is nfull
// unpredicated iterations (1 LDG.128 + 4 FADD, unroll 3, depth-3 pipeline),
// tiny predicated epilogue. smem combine, plain disjoint stores.
// No atomics, no zeroing, no cross-block sync, one launch.

#define VCOLS  64      // float4 per row
#define HL4    32      // float4 lanes per column half (128 cols = 512B)
#define TPB    256
#define SEED_M 1500    // half-window (6.7 sigma)
#define FULL   0xffffffffu

__global__ __launch_bounds__(TPB, 8) void gap_kernel(
    const float4* __restrict__ x,
    const int* __restrict__ b32,     // batch viewed as int32 words
    float4* __restrict__ out,
    int nrows, int nseg)
{
    __shared__ int    s_b[2];
    __shared__ float4 s_part[8][HL4];

    const int tid  = threadIdx.x;
    const int w    = tid >> 5;
    const int lane = tid & 31;
    const int g    = blockIdx.x >> 1;     // segment
    const int ch   = blockIdx.x & 1;      // column half

    // int64 vs int32 batch: sorted ids < nseg, so little-endian int64 puts a
    // zero high word at int32 index nrows-1.
    const int shift = (b32[nrows - 1] == 0) ? 1 : 0;

    // ---- warp 0: dual seeded lower_bound (g in lanes 0-15, g+1 in 16-31) ----
    if (w == 0) {
        const int half   = lane >> 4;
        const int hl     = lane & 15;
        const int target = g + half;

        long E  = (long)target * nrows / nseg;
        long lo = E - SEED_M; if (lo < 0) lo = 0;
        long hw = E + SEED_M; if (hw > nrows) hw = nrows;
        bool vlo = (lo == 0)     || (b32[(lo - 1) << shift] <  target);
        bool vhi = (hw == nrows) || (b32[(hw - 1) << shift] >= target);
        long rem = hw - lo;
        if (!(vlo && vhi)) { lo = 0; rem = nrows; }   // guaranteed-correct fallback

        const unsigned hmask = 0xFFFFu << (half * 16);
        while (__any_sync(FULL, rem > 0)) {
            long chunk = (rem + 16) / 17;             // 17-way partition
            bool lt = false;
            if (rem > 0) {
                long p = lo + chunk * (hl + 1) - 1;
                if (p < lo + rem) lt = (b32[p << shift] < target);
            }
            unsigned m = __ballot_sync(FULL, lt) & hmask;
            if (rem > 0) {
                int k = __popc(m);
                lo += (long)k * chunk;
                long r2 = rem - (long)k * chunk;
                rem = (r2 <= 0) ? 0 : ((r2 >= chunk) ? (chunk - 1) : r2);
            }
        }
        if (hl == 0) s_b[half] = (int)lo;
    }
    __syncthreads();
    const int lo  = s_b[0];
    const int hi  = s_b[1];
    const int cnt = hi - lo;

    const float4* xs = x + (size_t)ch * HL4 + lane;   // column offset

    // ---- stream rows lo+w, lo+w+8, ... ----
    float4 acc = make_float4(0.f, 0.f, 0.f, 0.f);
    const int nfull = cnt >> 3;           // unpredicated iterations per warp
    int k0 = 0;

    if (nfull >= 3) {
        const float4* p = xs + (size_t)(lo + w) * VCOLS;
        const size_t step = (size_t)8 * VCOLS;
        float4 va = p[0];
        float4 vb = p[step];
        float4 vc = p[2 * step];
        const int iters = nfull - 3;
        #pragma unroll 3
        for (int i = 0; i < iters; i++) {
            float4 vd = p[3 * step];               // unpredicated prefetch
            acc.x += va.x; acc.y += va.y; acc.z += va.z; acc.w += va.w;
            va = vb; vb = vc; vc = vd;
            p += step;
        }
        acc.x += va.x; acc.y += va.y; acc.z += va.z; acc.w += va.w;
        acc.x += vb.x; acc.y += vb.y; acc.z += vb.z; acc.w += vb.w;
        acc.x += vc.x; acc.y += vc.y; acc.z += vc.z; acc.w += vc.w;
        k0 = nfull;
    }
    // epilogue (and small-segment path): at most a few predicated rows
    for (int r = lo + w + (k0 << 3); r < hi; r += 8) {
        float4 v = xs[(size_t)r * VCOLS];
        acc.x += v.x; acc.y += v.y; acc.z += v.z; acc.w += v.w;
    }

    s_part[w][lane] = acc;
    __syncthreads();

    if (w == 0) {
        float4 a = s_part[0][lane];
        #pragma unroll
        for (int s = 1; s < 8; s++) {
            float4 b = s_part[s][lane];
            a.x += b.x; a.y += b.y; a.z += b.z; a.w += b.w;
        }
        // Disjoint (segment, half) output -> unconditional plain store
        // (also initializes empty segments over the poisoned buffer).
        out[(size_t)g * VCOLS + ch * HL4 + lane] = a;
    }
}

extern "C" void kernel_launch(void* const* d_in, const int* in_sizes, int n_in,
                              void* d_out, int out_size) {
    const float4* x  = (const float4*)d_in[0];
    const int* batch = (const int*)d_in[1];
    float4* out      = (float4*)d_out;

    const int nrows = in_sizes[1];        // 200000
    const int nseg  = out_size / 256;     // 512

    gap_kernel<<<nseg * 2, TPB>>>(x, batch, out, nrows, nseg);
}

// round 9
// speedup vs baseline: 1.0667x; 1.0667x over previous
#include <cuda_runtime.h>
#include <cuda_bf16.h>

// GraphAddPooling: out[g] = sum_{i: batch[i]==g} x[i]
// x: [200000, 256] fp32, batch: sorted (int32/int64, detected), out: [512,256] fp32.
//
// Single kernel, no atomics, no zeroing, no cross-block sync.
// One block per (segment, column half): 1024 blocks x 256 threads.
//   - seeded warp k-ary lower_bound: window E +/- 1500 (validity probes issued
//     concurrently with round-1 partition probes; full-search fallback) ->
//     3 dependent probe rounds, mostly L2-warm
//   - 8 row-streams x 32 float4-lanes (512B per warp, coalesced), depth-4
//     prefetch, plain loads
//   - smem combine, unconditional plain store (covers empty segments)
// Best measured engine: 35.46us kernel, 74.7% DRAM (5.92 TB/s) — ~86% of the
// B300 path-independent LTS cap. R4/R5/R7/R8 established that sync-fusion,
// warp-autonomous restructuring, and hand-unrolled steady loops all regress.

#define NCOLS   256
#define VCOLS   64      // float4 per full row
#define LANES   32      // float4 lanes per column half (128 cols = 512B)
#define STREAMS 8
#define TPB     256
#define SEED_M  1500    // half-window for seeded search (6.7 sigma)

// Plain k-ary lower_bound rounds on [lo, lo+rem).
__device__ __forceinline__ long klb_rounds(const int* __restrict__ b, int shift,
                                           long lo, long rem, int target, int lane) {
    while (rem > 0) {
        long chunk = (rem + 32) / 33;
        long p = lo + chunk * (lane + 1) - 1;
        bool lt = false;
        if (p < lo + rem) lt = (b[p << shift] < target);
        unsigned m = __ballot_sync(0xffffffffu, lt);
        int k = __popc(m);
        lo += (long)k * chunk;
        long r2 = rem - (long)k * chunk;
        rem = (r2 <= 0) ? 0 : ((r2 >= chunk) ? (chunk - 1) : r2);
    }
    return lo;
}

// Seeded lower_bound: round-1 partition probes + window-validity probes are
// independent loads issued together (one memory round), then 2 more rounds.
__device__ __forceinline__ int seeded_lower_bound(const int* __restrict__ b,
                                                  int shift, int n, int nseg,
                                                  int target, int lane) {
    long E = (long)target * n / nseg;
    long lo0 = E - SEED_M; if (lo0 < 0) lo0 = 0;
    long hi0 = E + SEED_M; if (hi0 > n) hi0 = n;
    long rem0 = hi0 - lo0;

    long chunk = (rem0 + 32) / 33;
    long p = lo0 + chunk * (lane + 1) - 1;
    bool lt = false;
    if (p < hi0) lt = (b[p << shift] < target);
    // validity probes (independent of partition probes; broadcast loads)
    bool vlo = (lo0 == 0) || (b[(lo0 - 1) << shift] < target);
    bool vhi = (hi0 == n) || (b[(hi0 - 1) << shift] >= target);
    unsigned m = __ballot_sync(0xffffffffu, lt);

    if (vlo && vhi) {
        int k = __popc(m);
        long lo = lo0 + (long)k * chunk;
        long r2 = rem0 - (long)k * chunk;
        long rem = (r2 <= 0) ? 0 : ((r2 >= chunk) ? (chunk - 1) : r2);
        return (int)klb_rounds(b, shift, lo, rem, target, lane);
    }
    // window missed (never for this data; guaranteed-correct fallback)
    return (int)klb_rounds(b, shift, 0, n, target, lane);
}

__global__ __launch_bounds__(TPB, 7) void gap_seg_kernel(
    const float4* __restrict__ x,
    const int* __restrict__ b32,     // batch viewed as int32 words
    float4* __restrict__ out,
    int nrows, int nseg)
{
    __shared__ int    s_bounds[2];
    __shared__ float4 s_part[STREAMS][LANES];

    const int g    = blockIdx.x >> 1;        // segment
    const int ch   = blockIdx.x & 1;         // column half
    const int tid  = threadIdx.x;
    const int lane = tid & (LANES - 1);      // float4 lane within half
    const int ys   = tid >> 5;               // row stream 0..7 (== warp id)

    // int64 vs int32 batch: sorted ids < nseg, so little-endian int64 puts a
    // zero high word at int32 index nrows-1.
    const int shift = (b32[nrows - 1] == 0) ? 1 : 0;

    if (ys < 2) {
        int r = seeded_lower_bound(b32, shift, nrows, nseg, g + ys, lane);
        if (lane == 0) s_bounds[ys] = r;
    }
    __syncthreads();
    const int lo = s_bounds[0];
    const int hi = s_bounds[1];

    const float4* xq = x + (size_t)ch * LANES + lane;   // column offset

    // Depth-4 pipelined stream over rows lo+ys, lo+ys+8, ...
    float4 acc = make_float4(0.f, 0.f, 0.f, 0.f);
    int r = lo + ys;

    float4 va = make_float4(0.f, 0.f, 0.f, 0.f);
    float4 vb = make_float4(0.f, 0.f, 0.f, 0.f);
    float4 vc = make_float4(0.f, 0.f, 0.f, 0.f);
    if (r < hi)                va = xq[(size_t)r * VCOLS];
    if (r + STREAMS < hi)      vb = xq[(size_t)(r + STREAMS) * VCOLS];
    if (r + 2 * STREAMS < hi)  vc = xq[(size_t)(r + 2 * STREAMS) * VCOLS];

    for (; r < hi; r += STREAMS) {
        float4 vd = make_float4(0.f, 0.f, 0.f, 0.f);
        if (r + 3 * STREAMS < hi) vd = xq[(size_t)(r + 3 * STREAMS) * VCOLS];
        acc.x += va.x; acc.y += va.y; acc.z += va.z; acc.w += va.w;
        va = vb; vb = vc; vc = vd;
    }

    s_part[ys][lane] = acc;
    __syncthreads();

    if (tid < LANES) {
        float4 a = s_part[0][tid];
        #pragma unroll
        for (int s = 1; s < STREAMS; s++) {
            float4 b = s_part[s][tid];
            a.x += b.x; a.y += b.y; a.z += b.z; a.w += b.w;
        }
        // Disjoint (segment, half) output -> unconditional plain store
        // (also initializes empty segments over the poisoned buffer).
        out[(size_t)g * VCOLS + ch * LANES + tid] = a;
    }
}

extern "C" void kernel_launch(void* const* d_in, const int* in_sizes, int n_in,
                              void* d_out, int out_size) {
    const float4* x  = (const float4*)d_in[0];
    const int* batch = (const int*)d_in[1];
    float4* out      = (float4*)d_out;

    const int nrows = in_sizes[1];        // 200000
    const int nseg  = out_size / NCOLS;   // 512

    gap_seg_kernel<<<nseg * 2, TPB>>>(x, batch, out, nrows, nseg);
}